// round 9
// baseline (speedup 1.0000x reference)
#include <cuda_runtime.h>
#include <cuda_fp16.h>

// Problem constants
#define HH 2048
#define WW 2048
#define NPIX (HH * WW)          // 4,194,304 pixels
#define NCH 8

constexpr int S0 = 1024, S1 = 512, S2 = 256, S3 = 128;
constexpr int N0 = S0 * S0, N1 = S1 * S1, N2 = S2 * S2, N3 = S3 * S3;
// Pair-slot layout: one 32B slot per (y,x) holding fp16 texels (x) and (x+1).
// Slot stride = 8 uints (32B). Offsets in uints:
constexpr unsigned POFF0 = 0;
constexpr unsigned POFF1 = POFF0 + (unsigned)N0 * 8;
constexpr unsigned POFF2 = POFF1 + (unsigned)N1 * 8;
constexpr unsigned POFF3 = POFF2 + (unsigned)N2 * 8;
constexpr size_t PAIR_ELEMS = (size_t)POFF3 + (size_t)N3 * 8;   // 44.56 MB

__device__ __align__(128) unsigned int g_pairs[PAIR_ELEMS];

// ---------------------------------------------------------------------------
// 256-bit load (sm_100+), 32B-aligned: one instruction, one 32B sector.
// ---------------------------------------------------------------------------
__device__ __forceinline__ void ldg256u(const unsigned int* __restrict__ p,
                                        unsigned int r[8]) {
    asm volatile("ld.global.nc.v8.b32 {%0,%1,%2,%3,%4,%5,%6,%7}, [%8];"
                 : "=r"(r[0]), "=r"(r[1]), "=r"(r[2]), "=r"(r[3]),
                   "=r"(r[4]), "=r"(r[5]), "=r"(r[6]), "=r"(r[7])
                 : "l"(p));
}

// ---------------------------------------------------------------------------
// Packed fp32x2 helpers (Blackwell dual-lane fp32 FMA, PTX-only).
// ---------------------------------------------------------------------------
using u64 = unsigned long long;

__device__ __forceinline__ u64 pk2(float x, float y) {
    u64 r;
    asm("mov.b64 %0, {%1, %2};" : "=l"(r) : "f"(x), "f"(y));
    return r;
}
__device__ __forceinline__ float2 unpk2(u64 v) {
    float2 f;
    asm("mov.b64 {%0, %1}, %2;" : "=f"(f.x), "=f"(f.y) : "l"(v));
    return f;
}
__device__ __forceinline__ u64 fma2(u64 a, u64 b, u64 c) {
    u64 d;
    asm("fma.rn.f32x2 %0, %1, %2, %3;" : "=l"(d) : "l"(a), "l"(b), "l"(c));
    return d;
}
__device__ __forceinline__ u64 mul2(u64 a, u64 b) {
    u64 d;
    asm("mul.rn.f32x2 %0, %1, %2;" : "=l"(d) : "l"(a), "l"(b));
    return d;
}
// half2 -> packed f32x2
__device__ __forceinline__ u64 h2_to_f2(unsigned int h) {
    float2 f = __half22float2(*reinterpret_cast<const __half2*>(&h));
    return pk2(f.x, f.y);
}

// ---------------------------------------------------------------------------
// Pair-slot builder for one texel index of one level.
// ---------------------------------------------------------------------------
__device__ __forceinline__ void build_one(const float* __restrict__ src,
                                          unsigned int* __restrict__ dst,
                                          int S, int idx) {
    int n = S * S;
    int x = idx & (S - 1);           // S is a power of two
    bool has_next = (x + 1 < S);

    float a[NCH], b[NCH];
#pragma unroll
    for (int c = 0; c < NCH; c++) {
        a[c] = src[(size_t)c * n + idx];
        b[c] = has_next ? src[(size_t)c * n + idx + 1] : 0.0f;
    }
    unsigned int r[8];
#pragma unroll
    for (int i = 0; i < 4; i++) {
        __half2 ha = __halves2half2(__float2half_rn(a[2 * i]), __float2half_rn(a[2 * i + 1]));
        __half2 hb = __halves2half2(__float2half_rn(b[2 * i]), __float2half_rn(b[2 * i + 1]));
        r[i]     = *reinterpret_cast<unsigned int*>(&ha);
        r[i + 4] = *reinterpret_cast<unsigned int*>(&hb);
    }
    uint4* d = reinterpret_cast<uint4*>(dst + (size_t)idx * 8);
    d[0] = make_uint4(r[0], r[1], r[2], r[3]);
    d[1] = make_uint4(r[4], r[5], r[6], r[7]);
}

// Single fused prepass over all four levels. No early PDL trigger: completion
// (and thus full g_pairs visibility) is signaled at kernel end.
__global__ void __launch_bounds__(256)
build_all_kernel(const float* __restrict__ t0, const float* __restrict__ t1,
                 const float* __restrict__ t2, const float* __restrict__ t3,
                 unsigned int* __restrict__ dst) {
    int idx = blockIdx.x * blockDim.x + threadIdx.x;
    if (idx < N0)                 { build_one(t0, dst + POFF0, S0, idx); return; }
    idx -= N0;
    if (idx < N1)                 { build_one(t1, dst + POFF1, S1, idx); return; }
    idx -= N1;
    if (idx < N2)                 { build_one(t2, dst + POFF2, S2, idx); return; }
    idx -= N2;
    if (idx < N3)                 { build_one(t3, dst + POFF3, S3, idx); }
}

// ---------------------------------------------------------------------------
// Coord/weight computation for one level. align_corners=False, grid=uv*2-1
// => g = uv*S - 0.5.  Addresses are clamped to valid slots; zeros padding is
// realized purely through zeroed weights, so loads are UNCONDITIONAL.
// ---------------------------------------------------------------------------
template <int S>
__device__ __forceinline__ void coords(float u, float v,
                                       unsigned& o0, unsigned& o1,
                                       float& wxA, float& wxB,
                                       float& wy0, float& wy1) {
    float gx = u * (float)S - 0.5f;
    float gy = v * (float)S - 0.5f;
    float xf = floorf(gx);
    float yf = floorf(gy);
    int x0 = (int)xf, y0 = (int)yf;
    int y1 = y0 + 1;
    float fx = gx - xf;
    float fy = gy - yf;

    bool lo = (x0 >= 0);
    int  xl = lo ? x0 : 0;
    wxA = lo ? (1.0f - fx) : fx;
    wxB = lo ? fx : 0.0f;

    bool v0 = (y0 >= 0) & (y0 < S);
    bool v1 = (y1 >= 0) & (y1 < S);
    wy0 = v0 ? (1.0f - fy) : 0.0f;
    wy1 = v1 ? fy : 0.0f;
    int yc0 = v0 ? y0 : 0;
    int yc1 = v1 ? y1 : (S - 1);

    o0 = ((unsigned)(yc0 * S + xl)) * 8u;
    o1 = ((unsigned)(yc1 * S + xl)) * 8u;
}

// Accumulate one level's contribution (packed f32x2 math, full fp32 precision).
// tx = wxA*A + wxB*B per row; acc += wy0*tx0 + wy1*tx1, all as f32x2.
__device__ __forceinline__ void accum_level(const unsigned int r0[8],
                                            const unsigned int r1[8],
                                            float wxA, float wxB,
                                            float wy0, float wy1,
                                            u64 acc[4]) {
    u64 wxA2 = pk2(wxA, wxA);
    u64 wxB2 = pk2(wxB, wxB);
    u64 wy02 = pk2(wy0, wy0);
    u64 wy12 = pk2(wy1, wy1);
#pragma unroll
    for (int i = 0; i < 4; i++) {
        u64 A0 = h2_to_f2(r0[i]);
        u64 B0 = h2_to_f2(r0[i + 4]);
        u64 A1 = h2_to_f2(r1[i]);
        u64 B1 = h2_to_f2(r1[i + 4]);
        u64 tx0 = fma2(B0, wxB2, mul2(A0, wxA2));
        u64 tx1 = fma2(B1, wxB2, mul2(A1, wxA2));
        acc[i] = fma2(tx0, wy02, acc[i]);
        acc[i] = fma2(tx1, wy12, acc[i]);
    }
}

// Process two levels: coords, 4 batched loads, accumulate.
template <int SA, int SB>
__device__ __forceinline__ void do_two_levels(unsigned pbaseA, unsigned pbaseB,
                                              float u, float v, u64 acc[4]) {
    unsigned oA0, oA1, oB0, oB1;
    float axA, axB, ay0, ay1;
    float bxA, bxB, by0, by1;
    coords<SA>(u, v, oA0, oA1, axA, axB, ay0, ay1);
    coords<SB>(u, v, oB0, oB1, bxA, bxB, by0, by1);

    unsigned int r0[8], r1[8], r2[8], r3[8];
    ldg256u(g_pairs + pbaseA + oA0, r0);
    ldg256u(g_pairs + pbaseA + oA1, r1);
    ldg256u(g_pairs + pbaseB + oB0, r2);
    ldg256u(g_pairs + pbaseB + oB1, r3);

    accum_level(r0, r1, axA, axB, ay0, ay1, acc);
    accum_level(r2, r3, bxA, bxB, by0, by1, acc);
}

// ---------------------------------------------------------------------------
// Main kernel: 1 thread per pixel, two level-halves, packed f32x2 math.
// PDL consumer: launches while the prepass still runs; uv loads (independent
// of g_pairs) overlap the producer, then cudaGridDependencySynchronize()
// gates the first texture access.
// ---------------------------------------------------------------------------
__global__ void __launch_bounds__(128, 12)
deferred_render_kernel(const float* __restrict__ uv, float* __restrict__ out) {
    int idx = blockIdx.x * blockDim.x + threadIdx.x;

    float u = __ldcs(uv + idx);          // streaming: don't pollute L2
    float v = __ldcs(uv + NPIX + idx);

    // Wait for the prepass (g_pairs producer) to complete.
    cudaGridDependencySynchronize();

    u64 acc[4];
#pragma unroll
    for (int i = 0; i < 4; i++) acc[i] = 0ull;   // +0.0f, +0.0f

    do_two_levels<S0, S1>(POFF0, POFF1, u, v, acc);
    do_two_levels<S2, S3>(POFF2, POFF3, u, v, acc);

#pragma unroll
    for (int i = 0; i < 4; i++) {
        float2 r = unpk2(acc[i]);
        __stcs(out + (size_t)(2 * i)     * NPIX + idx, r.x);
        __stcs(out + (size_t)(2 * i + 1) * NPIX + idx, r.y);
    }
}

// ---------------------------------------------------------------------------
// Launch. Inputs per metadata order: uv_tensor, iter_nr, tex0..tex3.
// ---------------------------------------------------------------------------
extern "C" void kernel_launch(void* const* d_in, const int* in_sizes, int n_in,
                              void* d_out, int out_size) {
    const float* uv   = (const float*)d_in[0];
    // d_in[1] = iter_nr (unused)
    const float* tex0 = (const float*)d_in[2];
    const float* tex1 = (const float*)d_in[3];
    const float* tex2 = (const float*)d_in[4];
    const float* tex3 = (const float*)d_in[5];

    unsigned int* scratch;
    cudaGetSymbolAddress((void**)&scratch, g_pairs);

    const int TOTAL = N0 + N1 + N2 + N3;
    build_all_kernel<<<(TOTAL + 255) / 256, 256>>>(tex0, tex1, tex2, tex3, scratch);

    // Main kernel as PDL secondary: may begin its prologue while the prepass
    // is still running; cudaGridDependencySynchronize() in-kernel gates the
    // g_pairs reads. Falls back to normal serialization if PDL is unavailable.
    cudaLaunchConfig_t cfg = {};
    cfg.gridDim = dim3(NPIX / 128, 1, 1);
    cfg.blockDim = dim3(128, 1, 1);
    cfg.dynamicSmemBytes = 0;
    cfg.stream = 0;
    cudaLaunchAttribute attrs[1];
    attrs[0].id = cudaLaunchAttributeProgrammaticStreamSerialization;
    attrs[0].val.programmaticStreamSerializationAllowed = 1;
    cfg.attrs = attrs;
    cfg.numAttrs = 1;
    cudaLaunchKernelEx(&cfg, deferred_render_kernel, uv, (float*)d_out);
}

// round 12
// speedup vs baseline: 1.0115x; 1.0115x over previous
#include <cuda_runtime.h>
#include <cuda_fp16.h>

// Problem constants
#define HH 2048
#define WW 2048
#define NPIX (HH * WW)          // 4,194,304 pixels
#define NCH 8

constexpr int S0 = 1024, S1 = 512, S2 = 256, S3 = 128;
constexpr int N0 = S0 * S0, N1 = S1 * S1, N2 = S2 * S2, N3 = S3 * S3;
// Pair-slot layout: one 32B slot per (y,x) holding fp16 texels (x) and (x+1).
// Slot stride = 8 uints (32B). Offsets in uints:
constexpr unsigned POFF0 = 0;
constexpr unsigned POFF1 = POFF0 + (unsigned)N0 * 8;
constexpr unsigned POFF2 = POFF1 + (unsigned)N1 * 8;
constexpr unsigned POFF3 = POFF2 + (unsigned)N2 * 8;
constexpr size_t PAIR_ELEMS = (size_t)POFF3 + (size_t)N3 * 8;   // 44.56 MB

__device__ __align__(128) unsigned int g_pairs[PAIR_ELEMS];

// ---------------------------------------------------------------------------
// 256-bit load (sm_100+), 32B-aligned: one instruction, one 32B sector.
// ---------------------------------------------------------------------------
__device__ __forceinline__ void ldg256u(const unsigned int* __restrict__ p,
                                        unsigned int r[8]) {
    asm volatile("ld.global.nc.v8.b32 {%0,%1,%2,%3,%4,%5,%6,%7}, [%8];"
                 : "=r"(r[0]), "=r"(r[1]), "=r"(r[2]), "=r"(r[3]),
                   "=r"(r[4]), "=r"(r[5]), "=r"(r[6]), "=r"(r[7])
                 : "l"(p));
}

// ---------------------------------------------------------------------------
// Pair-slot builder for one texel index of one level. Streaming reads (.cs):
// the fp32 sources are never re-read, so don't let them evict g_pairs in L2.
// ---------------------------------------------------------------------------
__device__ __forceinline__ void build_one(const float* __restrict__ src,
                                          unsigned int* __restrict__ dst,
                                          int S, int idx) {
    int n = S * S;
    int x = idx & (S - 1);           // S is a power of two
    bool has_next = (x + 1 < S);

    float a[NCH], b[NCH];
#pragma unroll
    for (int c = 0; c < NCH; c++) {
        a[c] = __ldcs(src + (size_t)c * n + idx);
        b[c] = has_next ? __ldcs(src + (size_t)c * n + idx + 1) : 0.0f;
    }
    unsigned int r[8];
#pragma unroll
    for (int i = 0; i < 4; i++) {
        __half2 ha = __halves2half2(__float2half_rn(a[2 * i]), __float2half_rn(a[2 * i + 1]));
        __half2 hb = __halves2half2(__float2half_rn(b[2 * i]), __float2half_rn(b[2 * i + 1]));
        r[i]     = *reinterpret_cast<unsigned int*>(&ha);
        r[i + 4] = *reinterpret_cast<unsigned int*>(&hb);
    }
    uint4* d = reinterpret_cast<uint4*>(dst + (size_t)idx * 8);
    d[0] = make_uint4(r[0], r[1], r[2], r[3]);
    d[1] = make_uint4(r[4], r[5], r[6], r[7]);
}

// Single fused prepass over all four levels, 2 texels per thread.
// No early PDL trigger: completion (=> g_pairs visibility) at kernel end.
constexpr int TOTAL_TEX = N0 + N1 + N2 + N3;   // 1,392,640
__global__ void __launch_bounds__(256)
build_all_kernel(const float* __restrict__ t0, const float* __restrict__ t1,
                 const float* __restrict__ t2, const float* __restrict__ t3,
                 unsigned int* __restrict__ dst) {
    int base = (blockIdx.x * blockDim.x + threadIdx.x) * 2;
#pragma unroll
    for (int k = 0; k < 2; k++) {
        int idx = base + k;
        if (idx >= TOTAL_TEX) return;
        if (idx < N0)      { build_one(t0, dst + POFF0, S0, idx); continue; }
        int i1 = idx - N0;
        if (i1 < N1)       { build_one(t1, dst + POFF1, S1, i1); continue; }
        int i2 = i1 - N1;
        if (i2 < N2)       { build_one(t2, dst + POFF2, S2, i2); continue; }
        int i3 = i2 - N2;
        build_one(t3, dst + POFF3, S3, i3);
    }
}

// ---------------------------------------------------------------------------
// Coord/weight computation for one level. align_corners=False, grid=uv*2-1
// => g = uv*S - 0.5.  Addresses are clamped to valid slots; zeros padding is
// realized purely through zeroed weights, so loads are UNCONDITIONAL.
// ---------------------------------------------------------------------------
template <int S>
__device__ __forceinline__ void coords(float u, float v,
                                       unsigned& o0, unsigned& o1,
                                       float& wxA, float& wxB,
                                       float& wy0, float& wy1) {
    float gx = u * (float)S - 0.5f;
    float gy = v * (float)S - 0.5f;
    float xf = floorf(gx);
    float yf = floorf(gy);
    int x0 = (int)xf, y0 = (int)yf;
    int y1 = y0 + 1;
    float fx = gx - xf;
    float fy = gy - yf;

    bool lo = (x0 >= 0);
    int  xl = lo ? x0 : 0;
    wxA = lo ? (1.0f - fx) : fx;
    wxB = lo ? fx : 0.0f;

    bool v0 = (y0 >= 0) & (y0 < S);
    bool v1 = (y1 >= 0) & (y1 < S);
    wy0 = v0 ? (1.0f - fy) : 0.0f;
    wy1 = v1 ? fy : 0.0f;
    int yc0 = v0 ? y0 : 0;
    int yc1 = v1 ? y1 : (S - 1);

    o0 = ((unsigned)(yc0 * S + xl)) * 8u;
    o1 = ((unsigned)(yc1 * S + xl)) * 8u;
}

// Accumulate one level's contribution (scalar fp32 math — measured best).
__device__ __forceinline__ void accum_level(const unsigned int r0[8],
                                            const unsigned int r1[8],
                                            float wxA, float wxB,
                                            float wy0, float wy1,
                                            float2 acc[4]) {
#pragma unroll
    for (int i = 0; i < 4; i++) {
        float2 A0 = __half22float2(*reinterpret_cast<const __half2*>(&r0[i]));
        float2 B0 = __half22float2(*reinterpret_cast<const __half2*>(&r0[i + 4]));
        float2 A1 = __half22float2(*reinterpret_cast<const __half2*>(&r1[i]));
        float2 B1 = __half22float2(*reinterpret_cast<const __half2*>(&r1[i + 4]));
        float tx0 = wxA * A0.x + wxB * B0.x;
        float ty0 = wxA * A0.y + wxB * B0.y;
        float tx1 = wxA * A1.x + wxB * B1.x;
        float ty1 = wxA * A1.y + wxB * B1.y;
        acc[i].x += wy0 * tx0 + wy1 * tx1;
        acc[i].y += wy0 * ty0 + wy1 * ty1;
    }
}

// Process two levels: coords, 4 batched loads, accumulate.
template <int SA, int SB>
__device__ __forceinline__ void do_two_levels(unsigned pbaseA, unsigned pbaseB,
                                              float u, float v, float2 acc[4]) {
    unsigned oA0, oA1, oB0, oB1;
    float axA, axB, ay0, ay1;
    float bxA, bxB, by0, by1;
    coords<SA>(u, v, oA0, oA1, axA, axB, ay0, ay1);
    coords<SB>(u, v, oB0, oB1, bxA, bxB, by0, by1);

    unsigned int r0[8], r1[8], r2[8], r3[8];
    ldg256u(g_pairs + pbaseA + oA0, r0);
    ldg256u(g_pairs + pbaseA + oA1, r1);
    ldg256u(g_pairs + pbaseB + oB0, r2);
    ldg256u(g_pairs + pbaseB + oB1, r3);

    accum_level(r0, r1, axA, axB, ay0, ay1, acc);
    accum_level(r2, r3, bxA, bxB, by0, by1, acc);
}

// ---------------------------------------------------------------------------
// Main kernel: 1 thread per pixel, two level-halves, scalar fp32 math.
// PDL consumer: uv loads (independent of g_pairs) overlap the producer; then
// cudaGridDependencySynchronize() gates the first texture access.
// ---------------------------------------------------------------------------
__global__ void __launch_bounds__(128, 12)
deferred_render_kernel(const float* __restrict__ uv, float* __restrict__ out) {
    int idx = blockIdx.x * blockDim.x + threadIdx.x;

    float u = __ldcs(uv + idx);          // streaming: don't pollute L2
    float v = __ldcs(uv + NPIX + idx);

    // Wait for the prepass (g_pairs producer) to complete.
    cudaGridDependencySynchronize();

    float2 acc[4];
#pragma unroll
    for (int i = 0; i < 4; i++) acc[i] = make_float2(0.0f, 0.0f);

    do_two_levels<S0, S1>(POFF0, POFF1, u, v, acc);
    do_two_levels<S2, S3>(POFF2, POFF3, u, v, acc);

#pragma unroll
    for (int i = 0; i < 4; i++) {
        __stcs(out + (size_t)(2 * i)     * NPIX + idx, acc[i].x);
        __stcs(out + (size_t)(2 * i + 1) * NPIX + idx, acc[i].y);
    }
}

// ---------------------------------------------------------------------------
// Launch. Inputs per metadata order: uv_tensor, iter_nr, tex0..tex3.
// ---------------------------------------------------------------------------
extern "C" void kernel_launch(void* const* d_in, const int* in_sizes, int n_in,
                              void* d_out, int out_size) {
    const float* uv   = (const float*)d_in[0];
    // d_in[1] = iter_nr (unused)
    const float* tex0 = (const float*)d_in[2];
    const float* tex1 = (const float*)d_in[3];
    const float* tex2 = (const float*)d_in[4];
    const float* tex3 = (const float*)d_in[5];

    unsigned int* scratch;
    cudaGetSymbolAddress((void**)&scratch, g_pairs);

    const int PREP_THREADS = (TOTAL_TEX + 1) / 2;
    build_all_kernel<<<(PREP_THREADS + 255) / 256, 256>>>(tex0, tex1, tex2, tex3, scratch);

    // Main kernel as PDL secondary: begins its prologue while the prepass is
    // still running; cudaGridDependencySynchronize() gates g_pairs reads.
    cudaLaunchConfig_t cfg = {};
    cfg.gridDim = dim3(NPIX / 128, 1, 1);
    cfg.blockDim = dim3(128, 1, 1);
    cfg.dynamicSmemBytes = 0;
    cfg.stream = 0;
    cudaLaunchAttribute attrs[1];
    attrs[0].id = cudaLaunchAttributeProgrammaticStreamSerialization;
    attrs[0].val.programmaticStreamSerializationAllowed = 1;
    cfg.attrs = attrs;
    cfg.numAttrs = 1;
    cudaLaunchKernelEx(&cfg, deferred_render_kernel, uv, (float*)d_out);
}

// round 13
// speedup vs baseline: 1.0166x; 1.0051x over previous
#include <cuda_runtime.h>
#include <cuda_fp16.h>

// Problem constants
#define HH 2048
#define WW 2048
#define NPIX (HH * WW)          // 4,194,304 pixels
#define NCH 8

constexpr int S0 = 1024, S1 = 512, S2 = 256, S3 = 128;
constexpr int N0 = S0 * S0, N1 = S1 * S1, N2 = S2 * S2, N3 = S3 * S3;
// Pair-slot layout: one 32B slot per (y,x) holding fp16 texels (x) and (x+1).
// Slot stride = 8 uints (32B). Offsets in uints:
constexpr unsigned POFF0 = 0;
constexpr unsigned POFF1 = POFF0 + (unsigned)N0 * 8;
constexpr unsigned POFF2 = POFF1 + (unsigned)N1 * 8;
constexpr unsigned POFF3 = POFF2 + (unsigned)N2 * 8;
constexpr size_t PAIR_ELEMS = (size_t)POFF3 + (size_t)N3 * 8;   // 44.56 MB

__device__ __align__(128) unsigned int g_pairs[PAIR_ELEMS];

// ---------------------------------------------------------------------------
// 256-bit load (sm_100+), 32B-aligned: one instruction, one 32B sector.
// ---------------------------------------------------------------------------
__device__ __forceinline__ void ldg256u(const unsigned int* __restrict__ p,
                                        unsigned int r[8]) {
    asm volatile("ld.global.nc.v8.b32 {%0,%1,%2,%3,%4,%5,%6,%7}, [%8];"
                 : "=r"(r[0]), "=r"(r[1]), "=r"(r[2]), "=r"(r[3]),
                   "=r"(r[4]), "=r"(r[5]), "=r"(r[6]), "=r"(r[7])
                 : "l"(p));
}

// ---------------------------------------------------------------------------
// Pair-slot builder for one texel index of one level (R8 version: plain
// loads, 1 texel per thread — the measured-fastest prepass).
// ---------------------------------------------------------------------------
__device__ __forceinline__ void build_one(const float* __restrict__ src,
                                          unsigned int* __restrict__ dst,
                                          int S, int idx) {
    int n = S * S;
    int x = idx & (S - 1);           // S is a power of two
    bool has_next = (x + 1 < S);

    float a[NCH], b[NCH];
#pragma unroll
    for (int c = 0; c < NCH; c++) {
        a[c] = src[(size_t)c * n + idx];
        b[c] = has_next ? src[(size_t)c * n + idx + 1] : 0.0f;
    }
    unsigned int r[8];
#pragma unroll
    for (int i = 0; i < 4; i++) {
        __half2 ha = __halves2half2(__float2half_rn(a[2 * i]), __float2half_rn(a[2 * i + 1]));
        __half2 hb = __halves2half2(__float2half_rn(b[2 * i]), __float2half_rn(b[2 * i + 1]));
        r[i]     = *reinterpret_cast<unsigned int*>(&ha);
        r[i + 4] = *reinterpret_cast<unsigned int*>(&hb);
    }
    uint4* d = reinterpret_cast<uint4*>(dst + (size_t)idx * 8);
    d[0] = make_uint4(r[0], r[1], r[2], r[3]);
    d[1] = make_uint4(r[4], r[5], r[6], r[7]);
}

// Single fused prepass over all four levels. No early PDL trigger: completion
// (and thus full g_pairs visibility) is signaled at kernel end.
constexpr int TOTAL_TEX = N0 + N1 + N2 + N3;   // 1,392,640
__global__ void __launch_bounds__(256)
build_all_kernel(const float* __restrict__ t0, const float* __restrict__ t1,
                 const float* __restrict__ t2, const float* __restrict__ t3,
                 unsigned int* __restrict__ dst) {
    int idx = blockIdx.x * blockDim.x + threadIdx.x;
    if (idx < N0)                 { build_one(t0, dst + POFF0, S0, idx); return; }
    idx -= N0;
    if (idx < N1)                 { build_one(t1, dst + POFF1, S1, idx); return; }
    idx -= N1;
    if (idx < N2)                 { build_one(t2, dst + POFF2, S2, idx); return; }
    idx -= N2;
    if (idx < N3)                 { build_one(t3, dst + POFF3, S3, idx); }
}

// ---------------------------------------------------------------------------
// Coord/weight computation for one level. align_corners=False, grid=uv*2-1
// => g = uv*S - 0.5.  Addresses are clamped to valid slots; zeros padding is
// realized purely through zeroed weights, so loads are UNCONDITIONAL.
// ---------------------------------------------------------------------------
template <int S>
__device__ __forceinline__ void coords(float u, float v,
                                       unsigned& o0, unsigned& o1,
                                       float& wxA, float& wxB,
                                       float& wy0, float& wy1) {
    float gx = u * (float)S - 0.5f;
    float gy = v * (float)S - 0.5f;
    float xf = floorf(gx);
    float yf = floorf(gy);
    int x0 = (int)xf, y0 = (int)yf;
    int y1 = y0 + 1;
    float fx = gx - xf;
    float fy = gy - yf;

    bool lo = (x0 >= 0);
    int  xl = lo ? x0 : 0;
    wxA = lo ? (1.0f - fx) : fx;
    wxB = lo ? fx : 0.0f;

    bool v0 = (y0 >= 0) & (y0 < S);
    bool v1 = (y1 >= 0) & (y1 < S);
    wy0 = v0 ? (1.0f - fy) : 0.0f;
    wy1 = v1 ? fy : 0.0f;
    int yc0 = v0 ? y0 : 0;
    int yc1 = v1 ? y1 : (S - 1);

    o0 = ((unsigned)(yc0 * S + xl)) * 8u;
    o1 = ((unsigned)(yc1 * S + xl)) * 8u;
}

// Accumulate one level's contribution (scalar fp32 math — measured best).
__device__ __forceinline__ void accum_level(const unsigned int r0[8],
                                            const unsigned int r1[8],
                                            float wxA, float wxB,
                                            float wy0, float wy1,
                                            float2 acc[4]) {
#pragma unroll
    for (int i = 0; i < 4; i++) {
        float2 A0 = __half22float2(*reinterpret_cast<const __half2*>(&r0[i]));
        float2 B0 = __half22float2(*reinterpret_cast<const __half2*>(&r0[i + 4]));
        float2 A1 = __half22float2(*reinterpret_cast<const __half2*>(&r1[i]));
        float2 B1 = __half22float2(*reinterpret_cast<const __half2*>(&r1[i + 4]));
        float tx0 = wxA * A0.x + wxB * B0.x;
        float ty0 = wxA * A0.y + wxB * B0.y;
        float tx1 = wxA * A1.x + wxB * B1.x;
        float ty1 = wxA * A1.y + wxB * B1.y;
        acc[i].x += wy0 * tx0 + wy1 * tx1;
        acc[i].y += wy0 * ty0 + wy1 * ty1;
    }
}

// Process two levels: coords, 4 batched loads, accumulate.
template <int SA, int SB>
__device__ __forceinline__ void do_two_levels(unsigned pbaseA, unsigned pbaseB,
                                              float u, float v, float2 acc[4]) {
    unsigned oA0, oA1, oB0, oB1;
    float axA, axB, ay0, ay1;
    float bxA, bxB, by0, by1;
    coords<SA>(u, v, oA0, oA1, axA, axB, ay0, ay1);
    coords<SB>(u, v, oB0, oB1, bxA, bxB, by0, by1);

    unsigned int r0[8], r1[8], r2[8], r3[8];
    ldg256u(g_pairs + pbaseA + oA0, r0);
    ldg256u(g_pairs + pbaseA + oA1, r1);
    ldg256u(g_pairs + pbaseB + oB0, r2);
    ldg256u(g_pairs + pbaseB + oB1, r3);

    accum_level(r0, r1, axA, axB, ay0, ay1, acc);
    accum_level(r2, r3, bxA, bxB, by0, by1, acc);
}

// ---------------------------------------------------------------------------
// Main kernel: 1 thread per pixel, two level-halves, scalar fp32 math.
// PDL consumer: uv loads (independent of g_pairs) overlap the producer; then
// cudaGridDependencySynchronize() gates the first texture access.
// ---------------------------------------------------------------------------
__global__ void __launch_bounds__(128, 12)
deferred_render_kernel(const float* __restrict__ uv, float* __restrict__ out) {
    int idx = blockIdx.x * blockDim.x + threadIdx.x;

    float u = __ldcs(uv + idx);          // streaming: don't pollute L2
    float v = __ldcs(uv + NPIX + idx);

    // Wait for the prepass (g_pairs producer) to complete.
    cudaGridDependencySynchronize();

    float2 acc[4];
#pragma unroll
    for (int i = 0; i < 4; i++) acc[i] = make_float2(0.0f, 0.0f);

    do_two_levels<S0, S1>(POFF0, POFF1, u, v, acc);
    do_two_levels<S2, S3>(POFF2, POFF3, u, v, acc);

#pragma unroll
    for (int i = 0; i < 4; i++) {
        __stcs(out + (size_t)(2 * i)     * NPIX + idx, acc[i].x);
        __stcs(out + (size_t)(2 * i + 1) * NPIX + idx, acc[i].y);
    }
}

// ---------------------------------------------------------------------------
// Launch. Inputs per metadata order: uv_tensor, iter_nr, tex0..tex3.
// ---------------------------------------------------------------------------
extern "C" void kernel_launch(void* const* d_in, const int* in_sizes, int n_in,
                              void* d_out, int out_size) {
    const float* uv   = (const float*)d_in[0];
    // d_in[1] = iter_nr (unused)
    const float* tex0 = (const float*)d_in[2];
    const float* tex1 = (const float*)d_in[3];
    const float* tex2 = (const float*)d_in[4];
    const float* tex3 = (const float*)d_in[5];

    unsigned int* scratch;
    cudaGetSymbolAddress((void**)&scratch, g_pairs);

    build_all_kernel<<<(TOTAL_TEX + 255) / 256, 256>>>(tex0, tex1, tex2, tex3, scratch);

    // Main kernel as PDL secondary: begins its prologue while the prepass is
    // still running; cudaGridDependencySynchronize() gates g_pairs reads.
    cudaLaunchConfig_t cfg = {};
    cfg.gridDim = dim3(NPIX / 128, 1, 1);
    cfg.blockDim = dim3(128, 1, 1);
    cfg.dynamicSmemBytes = 0;
    cfg.stream = 0;
    cudaLaunchAttribute attrs[1];
    attrs[0].id = cudaLaunchAttributeProgrammaticStreamSerialization;
    attrs[0].val.programmaticStreamSerializationAllowed = 1;
    cfg.attrs = attrs;
    cfg.numAttrs = 1;
    cudaLaunchKernelEx(&cfg, deferred_render_kernel, uv, (float*)d_out);
}